// round 12
// baseline (speedup 1.0000x reference)
#include <cuda_runtime.h>
#include <cuda_bf16.h>

// Encoder_57380763074770: batched GRU cell — ONE kernel, no inter-block sync.
// Key fix vs R11: W_ih is staged into shared with COALESCED float4 loads
// (~430 L1tex wavefronts) instead of per-thread strided row reads
// (~13,000 wavefronts — the actual R11 bottleneck). gi then reads shared
// with conflict-free stride-33 LDS.
//
// Inputs (metadata order):
//  0: x [64,17] f32   1: ip [64,8] i32      2: port [64,2] i32
//  3: hidden [1,1,128] 4: ip_emb [256,1]    5: port_emb [70000,4]
//  6: W_ih [384,33]    7: W_hh [384,128]    8: b_ih [384]   9: b_hh [384]
// Output 0: outputs [64,128] f32
// Output 1: new_hidden [128] f32 = outputs[63], at offset 64*128

#define H 128
#define FIN 33
#define STEPS 64
#define NT 384
#define WIH_ELEMS (3 * H * FIN)        // 12672 floats
#define WIH_F4    (WIH_ELEMS / 4)      // 3168 float4

__global__ void __launch_bounds__(NT, 1)
fused_kernel(const float* __restrict__ x,
             const int*   __restrict__ ip,
             const int*   __restrict__ port,
             const float* __restrict__ hidden,
             const float* __restrict__ ip_emb,
             const float* __restrict__ port_emb,
             const float* __restrict__ W_ih,
             const float* __restrict__ W_hh,
             const float* __restrict__ b_ih,
             const float* __restrict__ b_hh,
             float* __restrict__ out,
             int out_size)
{
    extern __shared__ float sm[];
    float* sW   = sm;                   // 12672: W_ih staged (row-major)
    float* s_xi = sm + WIH_ELEMS;       // 36 (33 used)
    float* s_gi = s_xi + 36;            // 384
    float* s_gh = s_gi + 3 * H;         // 384

    const int s    = blockIdx.x;        // step 0..63
    const int t    = threadIdx.x;       // 0..383
    const int lane = t & 31;
    const int warp = t >> 5;            // 0..11
    const int oi   = lane & 7;          // lane within octet
    const int oct  = lane >> 3;         // octet 0..3

    // ---- stage W_ih into shared: fully coalesced float4 (8-9 per thread) ----
    {
        const float4* src = reinterpret_cast<const float4*>(W_ih);
        float4* dst = reinterpret_cast<float4*>(sW);
        #pragma unroll
        for (int i = 0; i < 8; i++)
            dst[i * NT + t] = src[i * NT + t];
        const int r = 8 * NT + t;       // remainder: 3168 - 3072 = 96 elems
        if (r < WIH_F4) dst[r] = src[r];
    }

    // ---- xi[33] = concat(x[s], ip_emb[ip[s]], port_emb[port[s]]) ----
    if (t < 17) {
        s_xi[t] = x[s * 17 + t];
    } else if (t < 25) {
        s_xi[t] = ip_emb[ip[s * 8 + (t - 17)]];            // ip_emb dim=1
    } else if (t < 33) {
        int q = t - 25;
        s_xi[t] = port_emb[port[s * 2 + (q >> 2)] * 4 + (q & 3)];
    }

    // ---- gh: 12 warps x 32 rows; 8 lanes per row, width-8 shuffle tree ----
    {
        const float4* h4p = reinterpret_cast<const float4*>(hidden);
        float4 h4[4];
        #pragma unroll
        for (int k = 0; k < 4; k++)
            h4[k] = h4p[k * 8 + oi];

        const float4* W4 = reinterpret_cast<const float4*>(W_hh); // 32 f4/row
        #pragma unroll 4
        for (int p = 0; p < 8; p++) {
            const int j = warp * 32 + p * 4 + oct;         // row 0..383
            const float4* wr = W4 + j * (H / 4);
            float a0 = 0.f, a1 = 0.f;
            #pragma unroll
            for (int k = 0; k < 4; k++) {
                const float4 wv = wr[k * 8 + oi];          // octet = one 128B line
                a0 = fmaf(wv.x, h4[k].x, a0);
                a1 = fmaf(wv.y, h4[k].y, a1);
                a0 = fmaf(wv.z, h4[k].z, a0);
                a1 = fmaf(wv.w, h4[k].w, a1);
            }
            float aa = a0 + a1;
            aa += __shfl_down_sync(0xffffffffu, aa, 4, 8);
            aa += __shfl_down_sync(0xffffffffu, aa, 2, 8);
            aa += __shfl_down_sync(0xffffffffu, aa, 1, 8);
            if (oi == 0) s_gh[j] = aa + b_hh[j];
        }
    }
    __syncthreads();    // sW, s_xi, s_gh all ready

    // ---- gi[t] = xi . W_ih[t] + b_ih[t] — stride-33 LDS, conflict-free ----
    {
        float a = b_ih[t];
        const float* wr = sW + t * FIN;
        #pragma unroll
        for (int k = 0; k < FIN; k++)
            a = fmaf(s_xi[k], wr[k], a);
        s_gi[t] = a;
    }
    __syncthreads();

    // ---- gates: threads 0..127, one per hidden unit ----
    if (t < H) {
        const float i_r = s_gi[t];
        const float i_z = s_gi[t + H];
        const float i_n = s_gi[t + 2 * H];
        const float h_r = s_gh[t];
        const float h_z = s_gh[t + H];
        const float h_n = s_gh[t + 2 * H];
        const float h0v = hidden[t];

        const float r = 1.0f / (1.0f + __expf(-(i_r + h_r)));
        const float z = 1.0f / (1.0f + __expf(-(i_z + h_z)));
        const float n = tanhf(i_n + r * h_n);
        const float o = (1.0f - z) * n + z * h0v;

        out[s * H + t] = o;
        if (s == STEPS - 1 && out_size >= STEPS * H + H)
            out[STEPS * H + t] = o;                        // new_hidden
    }
}

extern "C" void kernel_launch(void* const* d_in, const int* in_sizes, int n_in,
                              void* d_out, int out_size)
{
    const float* x        = (const float*)d_in[0];
    const int*   ip       = (const int*)  d_in[1];
    const int*   port     = (const int*)  d_in[2];
    const float* hidden   = (const float*)d_in[3];
    const float* ip_emb   = (const float*)d_in[4];
    const float* port_emb = (const float*)d_in[5];
    const float* W_ih     = (const float*)d_in[6];
    const float* W_hh     = (const float*)d_in[7];
    const float* b_ih     = (const float*)d_in[8];
    const float* b_hh     = (const float*)d_in[9];

    const int smem = (WIH_ELEMS + 36 + 3 * H + 3 * H) * (int)sizeof(float); // ~53.9 KB
    static bool attr_set = false;
    if (!attr_set) {
        cudaFuncSetAttribute(fused_kernel,
                             cudaFuncAttributeMaxDynamicSharedMemorySize, smem);
        attr_set = true;
    }

    fused_kernel<<<STEPS, NT, smem>>>(x, ip, port, hidden, ip_emb, port_emb,
                                      W_ih, W_hh, b_ih, b_hh,
                                      (float*)d_out, out_size);
}

// round 13
// speedup vs baseline: 1.0294x; 1.0294x over previous
#include <cuda_runtime.h>
#include <cuda_bf16.h>

// Encoder_57380763074770: batched GRU cell — ONE kernel, no inter-block sync.
// Key fix vs R11: W_ih is staged into shared with COALESCED float4 loads
// (~430 L1tex wavefronts) instead of per-thread strided row reads
// (~13,000 wavefronts — the actual R11 bottleneck). gi then reads shared
// with conflict-free stride-33 LDS.
//
// Inputs (metadata order):
//  0: x [64,17] f32   1: ip [64,8] i32      2: port [64,2] i32
//  3: hidden [1,1,128] 4: ip_emb [256,1]    5: port_emb [70000,4]
//  6: W_ih [384,33]    7: W_hh [384,128]    8: b_ih [384]   9: b_hh [384]
// Output 0: outputs [64,128] f32
// Output 1: new_hidden [128] f32 = outputs[63], at offset 64*128

#define H 128
#define FIN 33
#define STEPS 64
#define NT 384
#define WIH_ELEMS (3 * H * FIN)        // 12672 floats
#define WIH_F4    (WIH_ELEMS / 4)      // 3168 float4

__global__ void __launch_bounds__(NT, 1)
fused_kernel(const float* __restrict__ x,
             const int*   __restrict__ ip,
             const int*   __restrict__ port,
             const float* __restrict__ hidden,
             const float* __restrict__ ip_emb,
             const float* __restrict__ port_emb,
             const float* __restrict__ W_ih,
             const float* __restrict__ W_hh,
             const float* __restrict__ b_ih,
             const float* __restrict__ b_hh,
             float* __restrict__ out,
             int out_size)
{
    extern __shared__ float sm[];
    float* sW   = sm;                   // 12672: W_ih staged (row-major)
    float* s_xi = sm + WIH_ELEMS;       // 36 (33 used)
    float* s_gi = s_xi + 36;            // 384
    float* s_gh = s_gi + 3 * H;         // 384

    const int s    = blockIdx.x;        // step 0..63
    const int t    = threadIdx.x;       // 0..383
    const int lane = t & 31;
    const int warp = t >> 5;            // 0..11
    const int oi   = lane & 7;          // lane within octet
    const int oct  = lane >> 3;         // octet 0..3

    // ---- stage W_ih into shared: fully coalesced float4 (8-9 per thread) ----
    {
        const float4* src = reinterpret_cast<const float4*>(W_ih);
        float4* dst = reinterpret_cast<float4*>(sW);
        #pragma unroll
        for (int i = 0; i < 8; i++)
            dst[i * NT + t] = src[i * NT + t];
        const int r = 8 * NT + t;       // remainder: 3168 - 3072 = 96 elems
        if (r < WIH_F4) dst[r] = src[r];
    }

    // ---- xi[33] = concat(x[s], ip_emb[ip[s]], port_emb[port[s]]) ----
    if (t < 17) {
        s_xi[t] = x[s * 17 + t];
    } else if (t < 25) {
        s_xi[t] = ip_emb[ip[s * 8 + (t - 17)]];            // ip_emb dim=1
    } else if (t < 33) {
        int q = t - 25;
        s_xi[t] = port_emb[port[s * 2 + (q >> 2)] * 4 + (q & 3)];
    }

    // ---- gh: 12 warps x 32 rows; 8 lanes per row, width-8 shuffle tree ----
    {
        const float4* h4p = reinterpret_cast<const float4*>(hidden);
        float4 h4[4];
        #pragma unroll
        for (int k = 0; k < 4; k++)
            h4[k] = h4p[k * 8 + oi];

        const float4* W4 = reinterpret_cast<const float4*>(W_hh); // 32 f4/row
        #pragma unroll 4
        for (int p = 0; p < 8; p++) {
            const int j = warp * 32 + p * 4 + oct;         // row 0..383
            const float4* wr = W4 + j * (H / 4);
            float a0 = 0.f, a1 = 0.f;
            #pragma unroll
            for (int k = 0; k < 4; k++) {
                const float4 wv = wr[k * 8 + oi];          // octet = one 128B line
                a0 = fmaf(wv.x, h4[k].x, a0);
                a1 = fmaf(wv.y, h4[k].y, a1);
                a0 = fmaf(wv.z, h4[k].z, a0);
                a1 = fmaf(wv.w, h4[k].w, a1);
            }
            float aa = a0 + a1;
            aa += __shfl_down_sync(0xffffffffu, aa, 4, 8);
            aa += __shfl_down_sync(0xffffffffu, aa, 2, 8);
            aa += __shfl_down_sync(0xffffffffu, aa, 1, 8);
            if (oi == 0) s_gh[j] = aa + b_hh[j];
        }
    }
    __syncthreads();    // sW, s_xi, s_gh all ready

    // ---- gi[t] = xi . W_ih[t] + b_ih[t] — stride-33 LDS, conflict-free ----
    {
        float a = b_ih[t];
        const float* wr = sW + t * FIN;
        #pragma unroll
        for (int k = 0; k < FIN; k++)
            a = fmaf(s_xi[k], wr[k], a);
        s_gi[t] = a;
    }
    __syncthreads();

    // ---- gates: threads 0..127, one per hidden unit ----
    if (t < H) {
        const float i_r = s_gi[t];
        const float i_z = s_gi[t + H];
        const float i_n = s_gi[t + 2 * H];
        const float h_r = s_gh[t];
        const float h_z = s_gh[t + H];
        const float h_n = s_gh[t + 2 * H];
        const float h0v = hidden[t];

        const float r = 1.0f / (1.0f + __expf(-(i_r + h_r)));
        const float z = 1.0f / (1.0f + __expf(-(i_z + h_z)));
        const float n = tanhf(i_n + r * h_n);
        const float o = (1.0f - z) * n + z * h0v;

        out[s * H + t] = o;
        if (s == STEPS - 1 && out_size >= STEPS * H + H)
            out[STEPS * H + t] = o;                        // new_hidden
    }
}

extern "C" void kernel_launch(void* const* d_in, const int* in_sizes, int n_in,
                              void* d_out, int out_size)
{
    const float* x        = (const float*)d_in[0];
    const int*   ip       = (const int*)  d_in[1];
    const int*   port     = (const int*)  d_in[2];
    const float* hidden   = (const float*)d_in[3];
    const float* ip_emb   = (const float*)d_in[4];
    const float* port_emb = (const float*)d_in[5];
    const float* W_ih     = (const float*)d_in[6];
    const float* W_hh     = (const float*)d_in[7];
    const float* b_ih     = (const float*)d_in[8];
    const float* b_hh     = (const float*)d_in[9];

    const int smem = (WIH_ELEMS + 36 + 3 * H + 3 * H) * (int)sizeof(float); // ~53.9 KB
    static bool attr_set = false;
    if (!attr_set) {
        cudaFuncSetAttribute(fused_kernel,
                             cudaFuncAttributeMaxDynamicSharedMemorySize, smem);
        attr_set = true;
    }

    fused_kernel<<<STEPS, NT, smem>>>(x, ip, port, hidden, ip_emb, port_emb,
                                      W_ih, W_hh, b_ih, b_hh,
                                      (float*)d_out, out_size);
}